// round 4
// baseline (speedup 1.0000x reference)
#include <cuda_runtime.h>
#include <cuda_bf16.h>

// KL divergence between diagonal Gaussians, reduced to a single flat sum:
//   S = sum over all B*N elements of:
//         log(s2/s1) + (s1 + (mask*(mu2-mu1))^2) / s2
//   out = 0.5 * S / B - n/2        (n = 256, B = 65536)
//
// Memory-bound: 5 fp32 arrays of 64MB each = 320MB read, scalar out (float32).

#define TOT_ELEMS (65536LL * 256LL)
#define TOT4      (TOT_ELEMS / 4)          // 4,194,304 float4 groups
#define NBLK      1184                     // 8 * 148 SMs
#define NTHR      256

__device__ double g_partials[NBLK];

__global__ __launch_bounds__(NTHR)
void kld_partial_kernel(const float4* __restrict__ mu1,
                        const float4* __restrict__ mu2,
                        const float4* __restrict__ s1,
                        const float4* __restrict__ s2,
                        const float4* __restrict__ mask)
{
    const long long stride = (long long)gridDim.x * blockDim.x;
    long long i = (long long)blockIdx.x * blockDim.x + threadIdx.x;

    double acc = 0.0;

    for (; i < TOT4; i += stride) {
        float4 a = mu1[i];
        float4 b = mu2[i];
        float4 p = s1[i];
        float4 q = s2[i];
        float4 m = mask[i];

        // nan_to_num on mu1
        float a0 = (a.x == a.x) ? a.x : 0.0f;
        float a1 = (a.y == a.y) ? a.y : 0.0f;
        float a2 = (a.z == a.z) ? a.z : 0.0f;
        float a3 = (a.w == a.w) ? a.w : 0.0f;

        float d0 = m.x * (b.x - a0);
        float d1 = m.y * (b.y - a1);
        float d2 = m.z * (b.z - a2);
        float d3 = m.w * (b.w - a3);

        // log(q/p) + (p + d^2)/q   per lane
        float f0 = __logf(__fdividef(q.x, p.x)) + __fdividef(p.x + d0 * d0, q.x);
        float f1 = __logf(__fdividef(q.y, p.y)) + __fdividef(p.y + d1 * d1, q.y);
        float f2 = __logf(__fdividef(q.z, p.z)) + __fdividef(p.z + d2 * d2, q.z);
        float f3 = __logf(__fdividef(q.w, p.w)) + __fdividef(p.w + d3 * d3, q.w);

        acc += (double)((f0 + f1) + (f2 + f3));
    }

    // Warp reduce (double)
    #pragma unroll
    for (int off = 16; off > 0; off >>= 1)
        acc += __shfl_down_sync(0xFFFFFFFFu, acc, off);

    __shared__ double warp_sums[NTHR / 32];
    int lane = threadIdx.x & 31;
    int wid  = threadIdx.x >> 5;
    if (lane == 0) warp_sums[wid] = acc;
    __syncthreads();

    if (wid == 0) {
        double v = (lane < NTHR / 32) ? warp_sums[lane] : 0.0;
        #pragma unroll
        for (int off = 4; off > 0; off >>= 1)
            v += __shfl_down_sync(0xFFFFFFFFu, v, off);
        if (lane == 0) g_partials[blockIdx.x] = v;
    }
}

__global__ __launch_bounds__(NTHR)
void kld_final_kernel(float* __restrict__ out)
{
    double acc = 0.0;
    for (int i = threadIdx.x; i < NBLK; i += NTHR)
        acc += g_partials[i];

    #pragma unroll
    for (int off = 16; off > 0; off >>= 1)
        acc += __shfl_down_sync(0xFFFFFFFFu, acc, off);

    __shared__ double warp_sums[NTHR / 32];
    int lane = threadIdx.x & 31;
    int wid  = threadIdx.x >> 5;
    if (lane == 0) warp_sums[wid] = acc;
    __syncthreads();

    if (wid == 0) {
        double v = (lane < NTHR / 32) ? warp_sums[lane] : 0.0;
        #pragma unroll
        for (int off = 4; off > 0; off >>= 1)
            v += __shfl_down_sync(0xFFFFFFFFu, v, off);
        if (lane == 0) {
            // mean_kl = 0.5 * S / B - n/2   (write as float32 per harness dtype)
            out[0] = (float)(0.5 * v / 65536.0 - 128.0);
        }
    }
}

extern "C" void kernel_launch(void* const* d_in, const int* in_sizes, int n_in,
                              void* d_out, int out_size)
{
    const float4* mu1  = (const float4*)d_in[0];
    const float4* mu2  = (const float4*)d_in[1];
    const float4* s1   = (const float4*)d_in[2];
    const float4* s2   = (const float4*)d_in[3];
    const float4* mask = (const float4*)d_in[4];

    kld_partial_kernel<<<NBLK, NTHR>>>(mu1, mu2, s1, s2, mask);
    kld_final_kernel<<<1, NTHR>>>((float*)d_out);
}